// round 9
// baseline (speedup 1.0000x reference)
#include <cuda_runtime.h>
#include <math.h>

#define NB 1024
#define TE 168
#define TD 24
#define NF 64
#define NH 128

typedef unsigned long long u64;

// ---- paired (row-pair) globals ----
__device__ float2 g_midp[(NB/2) * TE * NH];
__device__ float  g_wx  [NB * TE * NH];
__device__ float2 g_hmp [(NB/2) * NH];
__device__ float2 g_cmp [(NB/2) * NH];

// float4-packed k-major weights: gT4[kg*C + c] = {W[c][4kg..4kg+3]}
__device__ float4 gT4_eWih[16 * 512];
__device__ float4 gT4_eWhh[32 * 512];
__device__ float4 gT4_mWih[32 * 512];
__device__ float4 gT4_mWhh[32 * 512];
__device__ float4 gT4_dWih[32 * 512];
__device__ float4 gT4_dWhh[32 * 512];
__device__ float4 gT4_We [64 * 128];
__device__ float4 gT4_Wi [16 * 128];
__device__ float4 gT4_Vd [32 * 64];
__device__ float4 gT4_Wh [64 * 128];
__device__ float4 gT4_Wx [32 * 128];

__device__ __forceinline__ float ftanh(float x) {
    x = fminf(15.0f, fmaxf(-15.0f, x));
    const float e = __expf(2.0f * x);
    return __fdividef(e - 1.0f, e + 1.0f);
}
__device__ __forceinline__ float fsigm(float x) {
    return __fdividef(1.0f, 1.0f + __expf(-x));
}

__device__ __forceinline__ u64 dup2(float x) {
    u64 r; asm("mov.b64 %0, {%1, %1};" : "=l"(r) : "f"(x)); return r;
}
__device__ __forceinline__ float2 unp2(u64 v) {
    float2 r; asm("mov.b64 {%0, %1}, %2;" : "=f"(r.x), "=f"(r.y) : "l"(v)); return r;
}
__device__ __forceinline__ void ffma2(u64& d, u64 a, u64 b) {
    asm("fma.rn.f32x2 %0, %1, %2, %0;" : "+l"(d) : "l"(a), "l"(b));
}

// ---------------- Kernel 0: pack weights ----------------
__device__ __forceinline__ void packW(const float* __restrict__ W, float4* dst,
                                      int C, int K, int i0, int st)
{
    const int n = C * (K >> 2);
    for (int i = i0; i < n; i += st) {
        const int c = i % C, kg = i / C;
        const float* p = W + c * K + kg * 4;
        dst[i] = make_float4(p[0], p[1], p[2], p[3]);
    }
}

__global__ void k_tr(const float* __restrict__ eWih, const float* __restrict__ eWhh,
                     const float* __restrict__ mWih, const float* __restrict__ mWhh,
                     const float* __restrict__ dWih, const float* __restrict__ dWhh,
                     const float* __restrict__ We,   const float* __restrict__ Wi,
                     const float* __restrict__ Vd,   const float* __restrict__ Wh,
                     const float* __restrict__ Wx)
{
    const int i0 = blockIdx.x * blockDim.x + threadIdx.x;
    const int st = gridDim.x * blockDim.x;
    packW(eWih, gT4_eWih, 512, 64,  i0, st);
    packW(eWhh, gT4_eWhh, 512, 128, i0, st);
    packW(mWih, gT4_mWih, 512, 128, i0, st);
    packW(mWhh, gT4_mWhh, 512, 128, i0, st);
    packW(dWih, gT4_dWih, 512, 128, i0, st);
    packW(dWhh, gT4_dWhh, 512, 128, i0, st);
    packW(We,   gT4_We,   128, 256, i0, st);
    packW(Wi,   gT4_Wi,   128, 64,  i0, st);
    packW(Vd,   gT4_Vd,   64,  128, i0, st);
    packW(Wh,   gT4_Wh,   128, 256, i0, st);
    packW(Wx,   gT4_Wx,   128, 128, i0, st);
}

__device__ __forceinline__ void gemm_kg(u64& acc, const float4 w,
                                        const ulonglong2* __restrict__ act, int kg)
{
    const u64 w0 = dup2(w.x), w1 = dup2(w.y), w2 = dup2(w.z), w3 = dup2(w.w);
    const ulonglong2 a01 = act[2 * kg];
    const ulonglong2 a23 = act[2 * kg + 1];
    ffma2(acc, w0, a01.x); ffma2(acc, w1, a01.y);
    ffma2(acc, w2, a23.x); ffma2(acc, w3, a23.y);
}

// ---------------- Kernel 1: encoder + mid LSTM (1024 threads) ----------------
__global__ __launch_bounds__(1024, 1)
void k_enc_mid(const float* __restrict__ X,
               const float* __restrict__ Wi_b, const float* __restrict__ Vd_b,
               const float* __restrict__ ebih, const float* __restrict__ ebhh,
               const float* __restrict__ mbih, const float* __restrict__ mbhh)
{
    __shared__ __align__(16) float2 hcp [4][256];
    __shared__ __align__(16) float2 hmcp[4][256];
    __shared__ __align__(16) float2 xtp [4][64];
    __shared__ __align__(16) float2 xinp[4][64];
    __shared__ __align__(16) float2 t1p [4][128];
    __shared__ __align__(16) float2 scr [2048];   // gates out / stage partials

    const int tid = threadIdx.x;
    const int r0  = blockIdx.x * 8;
    const int p0  = blockIdx.x * 4;
    const int wno = tid >> 5, lane = tid & 31;

    {   // zero states (exactly 1024 entries)
        const int rp = tid >> 8, k = tid & 255;
        hcp [rp][k] = make_float2(0.f, 0.f);
        hmcp[rp][k] = make_float2(0.f, 0.f);
    }
    __syncthreads();

    for (int t = 0; t < TE; ++t) {
        if (tid < 512) {
            const int f = tid & 63, rp = (tid >> 6) & 3, half = tid >> 8;
            ((float*)&xtp[rp][f])[half] = X[((r0 + 2 * rp + half) * TE + t) * NF + f];
        }
        __syncthreads();

        // t1 partials: k-split halves (40 kg each)
        {
            const int j = tid & 127, rp = (tid >> 7) & 3, half = tid >> 9;
            const ulonglong2* hp = (const ulonglong2*)hcp[rp];
            u64 acc;
            if (!half) {
                acc = dup2(Wi_b[j]);
                #pragma unroll 8
                for (int kg = 0; kg < 40; ++kg)
                    gemm_kg(acc, gT4_We[kg * 128 + j], hp, kg);
            } else {
                acc = dup2(0.0f);
                #pragma unroll 8
                for (int kg = 40; kg < 64; ++kg)
                    gemm_kg(acc, gT4_We[kg * 128 + j], hp, kg);
                const ulonglong2* xp = (const ulonglong2*)xtp[rp];
                #pragma unroll
                for (int kg = 0; kg < 16; ++kg)
                    gemm_kg(acc, gT4_Wi[kg * 128 + j], xp, kg);
            }
            scr[half * 512 + rp * 128 + j] = unp2(acc);
        }
        __syncthreads();

        // fold + tanh
        if (tid < 512) {
            const int j = tid & 127, rp = tid >> 7;
            const float2 a = scr[rp * 128 + j], b = scr[512 + rp * 128 + j];
            t1p[rp][j] = make_float2(ftanh(a.x + b.x), ftanh(a.y + b.y));
        }
        __syncthreads();

        // s partials: k-split (16 kg each)
        if (tid < 512) {
            const int f = tid & 63, rp = (tid >> 6) & 3, half = tid >> 8;
            u64 acc = half ? dup2(0.0f) : dup2(Vd_b[f]);
            const ulonglong2* tp = (const ulonglong2*)t1p[rp];
            const int k0 = half * 16;
            #pragma unroll 8
            for (int kg = k0; kg < k0 + 16; ++kg)
                gemm_kg(acc, gT4_Vd[kg * 64 + f], tp, kg);
            scr[1024 + half * 256 + rp * 64 + f] = unp2(acc);
        }
        __syncthreads();

        // softmax + x_in : warps 0..7 (row = 2*rp + half)
        if (wno < 8) {
            const int rp = wno >> 1, half = wno & 1;
            const float2 a0 = scr[1024 + rp * 64 + lane];
            const float2 b0 = scr[1280 + rp * 64 + lane];
            const float2 a1 = scr[1024 + rp * 64 + lane + 32];
            const float2 b1 = scr[1280 + rp * 64 + lane + 32];
            float v0 = half ? (a0.y + b0.y) : (a0.x + b0.x);
            float v1 = half ? (a1.y + b1.y) : (a1.x + b1.x);
            float mx = fmaxf(v0, v1);
            #pragma unroll
            for (int o = 16; o; o >>= 1) mx = fmaxf(mx, __shfl_xor_sync(~0u, mx, o));
            float e0 = __expf(v0 - mx), e1 = __expf(v1 - mx);
            float sm = e0 + e1;
            #pragma unroll
            for (int o = 16; o; o >>= 1) sm += __shfl_xor_sync(~0u, sm, o);
            const float inv = __fdividef(1.0f, sm);
            const float2 x0 = xtp[rp][lane], x1 = xtp[rp][lane + 32];
            ((float*)&xinp[rp][lane])[half]      = (half ? x0.y : x0.x) * e0 * inv;
            ((float*)&xinp[rp][lane + 32])[half] = (half ? x1.y : x1.x) * e1 * inv;
        }
        __syncthreads();

        // enc gates: thread = (c, rpg), 2 row-pairs each
        {
            const int c = tid & 511, rpg = tid >> 9;
            const int ra = rpg * 2, rb = rpg * 2 + 1;
            const u64 bini = dup2(ebih[c] + ebhh[c]);
            u64 A0 = bini, A1 = bini;
            #pragma unroll 4
            for (int kg = 0; kg < 16; ++kg) {
                const float4 w = gT4_eWih[kg * 512 + c];
                gemm_kg(A0, w, (const ulonglong2*)xinp[ra], kg);
                gemm_kg(A1, w, (const ulonglong2*)xinp[rb], kg);
            }
            #pragma unroll 4
            for (int kg = 0; kg < 32; ++kg) {
                const float4 w = gT4_eWhh[kg * 512 + c];
                gemm_kg(A0, w, (const ulonglong2*)hcp[ra], kg);
                gemm_kg(A1, w, (const ulonglong2*)hcp[rb], kg);
            }
            scr[ra * 512 + c] = unp2(A0);
            scr[rb * 512 + c] = unp2(A1);
        }
        __syncthreads();

        // enc LSTM update: 1024 threads, one scalar half each
        {
            const int j = tid & 127, rp = (tid >> 7) & 3, half = tid >> 9;
            const float gi = ((const float*)&scr[rp * 512 + j      ])[half];
            const float gf = ((const float*)&scr[rp * 512 + j + 128])[half];
            const float gg = ((const float*)&scr[rp * 512 + j + 256])[half];
            const float go = ((const float*)&scr[rp * 512 + j + 384])[half];
            const float co = ((const float*)&hcp[rp][128 + j])[half];
            const float cn = fsigm(gf) * co + fsigm(gi) * ftanh(gg);
            const float hn = fsigm(go) * ftanh(cn);
            ((float*)&hcp[rp][j])[half]       = hn;
            ((float*)&hcp[rp][128 + j])[half] = cn;
        }
        __syncthreads();

        // mid gates
        {
            const int c = tid & 511, rpg = tid >> 9;
            const int ra = rpg * 2, rb = rpg * 2 + 1;
            const u64 bini = dup2(mbih[c] + mbhh[c]);
            u64 A0 = bini, A1 = bini;
            #pragma unroll 4
            for (int kg = 0; kg < 32; ++kg) {
                const float4 w = gT4_mWih[kg * 512 + c];
                gemm_kg(A0, w, (const ulonglong2*)hcp[ra], kg);
                gemm_kg(A1, w, (const ulonglong2*)hcp[rb], kg);
            }
            #pragma unroll 4
            for (int kg = 0; kg < 32; ++kg) {
                const float4 w = gT4_mWhh[kg * 512 + c];
                gemm_kg(A0, w, (const ulonglong2*)hmcp[ra], kg);
                gemm_kg(A1, w, (const ulonglong2*)hmcp[rb], kg);
            }
            scr[ra * 512 + c] = unp2(A0);
            scr[rb * 512 + c] = unp2(A1);
        }
        __syncthreads();

        // mid LSTM update + g_mid store (scalar halves)
        {
            const int j = tid & 127, rp = (tid >> 7) & 3, half = tid >> 9;
            const float gi = ((const float*)&scr[rp * 512 + j      ])[half];
            const float gf = ((const float*)&scr[rp * 512 + j + 128])[half];
            const float gg = ((const float*)&scr[rp * 512 + j + 256])[half];
            const float go = ((const float*)&scr[rp * 512 + j + 384])[half];
            const float co = ((const float*)&hmcp[rp][128 + j])[half];
            const float cn = fsigm(gf) * co + fsigm(gi) * ftanh(gg);
            const float hn = fsigm(go) * ftanh(cn);
            ((float*)&hmcp[rp][j])[half]       = hn;
            ((float*)&hmcp[rp][128 + j])[half] = cn;
            ((float*)&g_midp[((p0 + rp) * TE + t) * NH + j])[half] = hn;
        }
        __syncthreads();
    }

    {
        const int j = tid & 127, rp = (tid >> 7) & 3, half = tid >> 9;
        ((float*)&g_hmp[(p0 + rp) * NH + j])[half] = ((const float*)&hmcp[rp][j])[half];
        ((float*)&g_cmp[(p0 + rp) * NH + j])[half] = ((const float*)&hmcp[rp][128 + j])[half];
    }
}

// ---------------- Kernel 2: wx_mid ----------------
__global__ __launch_bounds__(256, 1)
void k_wx(const float* __restrict__ Wx_b)
{
    __shared__ __align__(16) float2 msp[16][128];
    const int tid = threadIdx.x;
    const int ub  = blockIdx.x * 16;

    for (int i = tid; i < 16 * 128; i += 256)
        msp[i >> 7][i & 127] = g_midp[ub * NH + i];
    __syncthreads();

    const int j = tid & 127, rg = tid >> 7;
    const u64 bini = dup2(Wx_b[j]);
    u64 acc[8];
    #pragma unroll
    for (int u = 0; u < 8; ++u) acc[u] = bini;

    #pragma unroll 4
    for (int kg = 0; kg < 32; ++kg) {
        const float4 w = gT4_Wx[kg * 128 + j];
        #pragma unroll
        for (int u = 0; u < 8; ++u)
            gemm_kg(acc[u], w, (const ulonglong2*)msp[rg * 8 + u], kg);
    }
    #pragma unroll
    for (int u = 0; u < 8; ++u) {
        const int gu = ub + rg * 8 + u;
        const int pair = gu / TE, tt = gu % TE;
        const float2 r = unp2(acc[u]);
        g_wx[((2 * pair)     * TE + tt) * NH + j] = r.x;
        g_wx[((2 * pair + 1) * TE + tt) * NH + j] = r.y;
    }
}

// ---------------- Kernel 3: decoder (1024 threads) ----------------
__global__ __launch_bounds__(1024, 1)
void k_dec(const float* __restrict__ V_w,  const float* __restrict__ V_b,
           const float* __restrict__ dbih, const float* __restrict__ dbhh,
           const float* __restrict__ regw, const float* __restrict__ regb,
           float* __restrict__ out)
{
    __shared__ __align__(16) float2 hicp[4][256];
    __shared__ __align__(16) float2 qsp [4][128];
    __shared__ __align__(16) float2 ssp2[4][TE];
    __shared__ __align__(16) float2 dinp[4][128];
    __shared__ __align__(16) float2 scr [2048];

    const int tid = threadIdx.x;
    const int r0  = blockIdx.x * 8;
    const int p0  = blockIdx.x * 4;
    const int wno = tid >> 5, lane = tid & 31;

    const float4 vw4 = ((const float4*)V_w)[lane];
    const float  vb  = V_b[0];

    {   // load state (exactly 1024 entries)
        const int rp = tid >> 8, k = tid & 255;
        hicp[rp][k] = (k < 128) ? g_hmp[(p0 + rp) * NH + k]
                                : g_cmp[(p0 + rp) * NH + (k - 128)];
    }
    __syncthreads();

    for (int td = 0; td < TD; ++td) {
        // q partials: k-split (32 kg each)
        {
            const int j = tid & 127, rp = (tid >> 7) & 3, half = tid >> 9;
            u64 acc = dup2(0.0f);
            const ulonglong2* hp = (const ulonglong2*)hicp[rp];
            const int k0 = half * 32;
            #pragma unroll 8
            for (int kg = k0; kg < k0 + 32; ++kg)
                gemm_kg(acc, gT4_Wh[kg * 128 + j], hp, kg);
            scr[half * 512 + rp * 128 + j] = unp2(acc);
        }
        __syncthreads();
        if (tid < 512) {
            const int j = tid & 127, rp = tid >> 7;
            const float2 a = scr[rp * 128 + j], b = scr[512 + rp * 128 + j];
            qsp[rp][j] = make_float2(a.x + b.x, a.y + b.y);
        }
        __syncthreads();

        // scores: 32 warps over 8*TE tasks
        for (int s = wno; s < 8 * TE; s += 32) {
            const int r = s / TE, tt = s % TE;
            const int rp = r >> 1, half = r & 1;
            const float4 x = ((const float4*)(g_wx + ((r0 + r) * TE + tt) * NH))[lane];
            const float2 q0 = qsp[rp][4 * lane],     q1 = qsp[rp][4 * lane + 1];
            const float2 q2 = qsp[rp][4 * lane + 2], q3 = qsp[rp][4 * lane + 3];
            float acc;
            acc =      ftanh((half ? q0.y : q0.x) + x.x) * vw4.x;
            acc = fmaf(ftanh((half ? q1.y : q1.x) + x.y), vw4.y, acc);
            acc = fmaf(ftanh((half ? q2.y : q2.x) + x.z), vw4.z, acc);
            acc = fmaf(ftanh((half ? q3.y : q3.x) + x.w), vw4.w, acc);
            #pragma unroll
            for (int o = 16; o; o >>= 1) acc += __shfl_xor_sync(~0u, acc, o);
            if (lane == 0) ((float*)&ssp2[rp][tt])[half] = acc + vb;
        }
        __syncthreads();

        // din partials: t-split (84 each)
        {
            const int j = tid & 127, rp = (tid >> 7) & 3, half = tid >> 9;
            u64 acc = dup2(0.0f);
            const u64* sp = (const u64*)ssp2[rp];
            const float2* mp = g_midp + ((p0 + rp) * TE) * NH + j;
            const int t0 = half * 84;
            #pragma unroll 4
            for (int tt = t0; tt < t0 + 84; ++tt) {
                const u64 m2 = *(const u64*)(mp + tt * NH);
                ffma2(acc, sp[tt], m2);
            }
            scr[half * 512 + rp * 128 + j] = unp2(acc);
        }
        __syncthreads();
        if (tid < 512) {
            const int j = tid & 127, rp = tid >> 7;
            const float2 a = scr[rp * 128 + j], b = scr[512 + rp * 128 + j];
            dinp[rp][j] = make_float2(a.x + b.x, a.y + b.y);
        }
        __syncthreads();

        // dec gates: (c, rpg)
        {
            const int c = tid & 511, rpg = tid >> 9;
            const int ra = rpg * 2, rb = rpg * 2 + 1;
            const u64 bini = dup2(dbih[c] + dbhh[c]);
            u64 A0 = bini, A1 = bini;
            #pragma unroll 4
            for (int kg = 0; kg < 32; ++kg) {
                const float4 w = gT4_dWih[kg * 512 + c];
                gemm_kg(A0, w, (const ulonglong2*)dinp[ra], kg);
                gemm_kg(A1, w, (const ulonglong2*)dinp[rb], kg);
            }
            #pragma unroll 4
            for (int kg = 0; kg < 32; ++kg) {
                const float4 w = gT4_dWhh[kg * 512 + c];
                gemm_kg(A0, w, (const ulonglong2*)hicp[ra], kg);
                gemm_kg(A1, w, (const ulonglong2*)hicp[rb], kg);
            }
            scr[ra * 512 + c] = unp2(A0);
            scr[rb * 512 + c] = unp2(A1);
        }
        __syncthreads();

        // dec LSTM update (scalar halves)
        {
            const int j = tid & 127, rp = (tid >> 7) & 3, half = tid >> 9;
            const float gi = ((const float*)&scr[rp * 512 + j      ])[half];
            const float gf = ((const float*)&scr[rp * 512 + j + 128])[half];
            const float gg = ((const float*)&scr[rp * 512 + j + 256])[half];
            const float go = ((const float*)&scr[rp * 512 + j + 384])[half];
            const float co = ((const float*)&hicp[rp][128 + j])[half];
            const float cn = fsigm(gf) * co + fsigm(gi) * ftanh(gg);
            const float hn = fsigm(go) * ftanh(cn);
            ((float*)&hicp[rp][j])[half]       = hn;
            ((float*)&hicp[rp][128 + j])[half] = cn;
        }
        __syncthreads();

        // out head: warps 0..7
        if (wno < 8) {
            const int rp = wno >> 1, half = wno & 1;
            const float2 h0 = hicp[rp][lane],      h1 = hicp[rp][lane + 32];
            const float2 h2 = hicp[rp][lane + 64], h3 = hicp[rp][lane + 96];
            float acc =       (half ? h0.y : h0.x) * regw[lane];
            acc = fmaf((half ? h1.y : h1.x), regw[lane + 32], acc);
            acc = fmaf((half ? h2.y : h2.x), regw[lane + 64], acc);
            acc = fmaf((half ? h3.y : h3.x), regw[lane + 96], acc);
            #pragma unroll
            for (int o = 16; o; o >>= 1) acc += __shfl_xor_sync(~0u, acc, o);
            if (lane == 0) out[(r0 + wno) * TD + td] = acc + regb[0];
        }
        __syncthreads();
    }
}

extern "C" void kernel_launch(void* const* d_in, const int* in_sizes, int n_in,
                              void* d_out, int out_size)
{
    const float* X    = (const float*)d_in[0];
    const float* Wi_w = (const float*)d_in[2];
    const float* Wi_b = (const float*)d_in[3];
    const float* We_w = (const float*)d_in[4];
    const float* Vd_w = (const float*)d_in[5];
    const float* Vd_b = (const float*)d_in[6];
    const float* eWih = (const float*)d_in[7];
    const float* eWhh = (const float*)d_in[8];
    const float* ebih = (const float*)d_in[9];
    const float* ebhh = (const float*)d_in[10];
    const float* mWih = (const float*)d_in[11];
    const float* mWhh = (const float*)d_in[12];
    const float* mbih = (const float*)d_in[13];
    const float* mbhh = (const float*)d_in[14];
    const float* Wx_w = (const float*)d_in[15];
    const float* Wx_b = (const float*)d_in[16];
    const float* Wh_w = (const float*)d_in[17];
    const float* V_w  = (const float*)d_in[18];
    const float* V_b  = (const float*)d_in[19];
    const float* dWih = (const float*)d_in[20];
    const float* dWhh = (const float*)d_in[21];
    const float* dbih = (const float*)d_in[22];
    const float* dbhh = (const float*)d_in[23];
    const float* regw = (const float*)d_in[24];
    const float* regb = (const float*)d_in[25];

    k_tr<<<256, 256>>>(eWih, eWhh, mWih, mWhh, dWih, dWhh,
                       We_w, Wi_w, Vd_w, Wh_w, Wx_w);
    k_enc_mid<<<NB / 8, 1024>>>(X, Wi_b, Vd_b, ebih, ebhh, mbih, mbhh);
    k_wx<<<(NB / 2 * TE) / 16, 256>>>(Wx_b);
    k_dec<<<NB / 8, 1024>>>(V_w, V_b, dbih, dbhh, regw, regb, (float*)d_out);
}

// round 10
// speedup vs baseline: 1.1483x; 1.1483x over previous
#include <cuda_runtime.h>
#include <cuda_fp16.h>
#include <math.h>

#define NB 1024
#define TE 168
#define TD 24
#define NF 64
#define NH 128

typedef unsigned long long u64;

// ---- paired (row-pair) globals ----
__device__ float2 g_midp[(NB/2) * TE * NH];
__device__ float  g_wx  [NB * TE * NH];
__device__ float2 g_hmp [(NB/2) * NH];
__device__ float2 g_cmp [(NB/2) * NH];

// half2x2-packed k-major weights: gU2[kg*C + c] = 4 halves {W[c][4kg..4kg+3]}
__device__ uint2 gU2_eWih[16 * 512];
__device__ uint2 gU2_eWhh[32 * 512];
__device__ uint2 gU2_mWih[32 * 512];
__device__ uint2 gU2_mWhh[32 * 512];
__device__ uint2 gU2_dWih[32 * 512];
__device__ uint2 gU2_dWhh[32 * 512];
__device__ uint2 gU2_We [64 * 128];
__device__ uint2 gU2_Wi [16 * 128];
__device__ uint2 gU2_Vd [32 * 64];
__device__ uint2 gU2_Wh [64 * 128];
__device__ uint2 gU2_Wx [32 * 128];

__device__ __forceinline__ float ftanh(float x) {
    x = fminf(15.0f, fmaxf(-15.0f, x));
    const float e = __expf(2.0f * x);
    return __fdividef(e - 1.0f, e + 1.0f);
}
__device__ __forceinline__ float fsigm(float x) {
    return __fdividef(1.0f, 1.0f + __expf(-x));
}

__device__ __forceinline__ u64 dup2(float x) {
    u64 r; asm("mov.b64 %0, {%1, %1};" : "=l"(r) : "f"(x)); return r;
}
__device__ __forceinline__ float2 unp2(u64 v) {
    float2 r; asm("mov.b64 {%0, %1}, %2;" : "=f"(r.x), "=f"(r.y) : "l"(v)); return r;
}
__device__ __forceinline__ void ffma2(u64& d, u64 a, u64 b) {
    asm("fma.rn.f32x2 %0, %1, %2, %0;" : "+l"(d) : "l"(a), "l"(b));
}

// load 4 fp16 weights, expand to fp32x4
__device__ __forceinline__ float4 ldw(const uint2* __restrict__ p, int idx) {
    const uint2 v = p[idx];
    const float2 lo = __half22float2(*(const __half2*)&v.x);
    const float2 hi = __half22float2(*(const __half2*)&v.y);
    return make_float4(lo.x, lo.y, hi.x, hi.y);
}

// ---------------- Kernel 0: pack weights (fp16, k-major) ----------------
__device__ __forceinline__ unsigned pk2(float a, float b) {
    const __half2 h = __floats2half2_rn(a, b);
    return *(const unsigned*)&h;
}
__device__ __forceinline__ void packW(const float* __restrict__ W, uint2* dst,
                                      int C, int K, int i0, int st)
{
    const int n = C * (K >> 2);
    for (int i = i0; i < n; i += st) {
        const int c = i % C, kg = i / C;
        const float* p = W + c * K + kg * 4;
        dst[i] = make_uint2(pk2(p[0], p[1]), pk2(p[2], p[3]));
    }
}

__global__ void k_tr(const float* __restrict__ eWih, const float* __restrict__ eWhh,
                     const float* __restrict__ mWih, const float* __restrict__ mWhh,
                     const float* __restrict__ dWih, const float* __restrict__ dWhh,
                     const float* __restrict__ We,   const float* __restrict__ Wi,
                     const float* __restrict__ Vd,   const float* __restrict__ Wh,
                     const float* __restrict__ Wx)
{
    const int i0 = blockIdx.x * blockDim.x + threadIdx.x;
    const int st = gridDim.x * blockDim.x;
    packW(eWih, gU2_eWih, 512, 64,  i0, st);
    packW(eWhh, gU2_eWhh, 512, 128, i0, st);
    packW(mWih, gU2_mWih, 512, 128, i0, st);
    packW(mWhh, gU2_mWhh, 512, 128, i0, st);
    packW(dWih, gU2_dWih, 512, 128, i0, st);
    packW(dWhh, gU2_dWhh, 512, 128, i0, st);
    packW(We,   gU2_We,   128, 256, i0, st);
    packW(Wi,   gU2_Wi,   128, 64,  i0, st);
    packW(Vd,   gU2_Vd,   64,  128, i0, st);
    packW(Wh,   gU2_Wh,   128, 256, i0, st);
    packW(Wx,   gU2_Wx,   128, 128, i0, st);
}

__device__ __forceinline__ void gemm_kg(u64& acc, const float4 w,
                                        const ulonglong2* __restrict__ act, int kg)
{
    const u64 w0 = dup2(w.x), w1 = dup2(w.y), w2 = dup2(w.z), w3 = dup2(w.w);
    const ulonglong2 a01 = act[2 * kg];
    const ulonglong2 a23 = act[2 * kg + 1];
    ffma2(acc, w0, a01.x); ffma2(acc, w1, a01.y);
    ffma2(acc, w2, a23.x); ffma2(acc, w3, a23.y);
}

// ---------------- Kernel 1: encoder + mid LSTM (1024 threads) ----------------
__global__ __launch_bounds__(1024, 1)
void k_enc_mid(const float* __restrict__ X,
               const float* __restrict__ Wi_b, const float* __restrict__ Vd_b,
               const float* __restrict__ ebih, const float* __restrict__ ebhh,
               const float* __restrict__ mbih, const float* __restrict__ mbhh)
{
    __shared__ __align__(16) float2 hcp [4][256];
    __shared__ __align__(16) float2 hmcp[4][256];
    __shared__ __align__(16) float2 xtp [4][64];
    __shared__ __align__(16) float2 xinp[4][64];
    __shared__ __align__(16) float2 t1p [4][128];
    __shared__ __align__(16) float2 scr [2048];

    const int tid = threadIdx.x;
    const int r0  = blockIdx.x * 8;
    const int p0  = blockIdx.x * 4;
    const int wno = tid >> 5, lane = tid & 31;

    {
        const int rp = tid >> 8, k = tid & 255;
        hcp [rp][k] = make_float2(0.f, 0.f);
        hmcp[rp][k] = make_float2(0.f, 0.f);
    }
    __syncthreads();

    for (int t = 0; t < TE; ++t) {
        if (tid < 512) {
            const int f = tid & 63, rp = (tid >> 6) & 3, half = tid >> 8;
            ((float*)&xtp[rp][f])[half] = X[((r0 + 2 * rp + half) * TE + t) * NF + f];
        }
        __syncthreads();

        // t1 partials: k-split halves
        {
            const int j = tid & 127, rp = (tid >> 7) & 3, half = tid >> 9;
            const ulonglong2* hp = (const ulonglong2*)hcp[rp];
            u64 acc;
            if (!half) {
                acc = dup2(Wi_b[j]);
                #pragma unroll 8
                for (int kg = 0; kg < 40; ++kg)
                    gemm_kg(acc, ldw(gU2_We, kg * 128 + j), hp, kg);
            } else {
                acc = dup2(0.0f);
                #pragma unroll 8
                for (int kg = 40; kg < 64; ++kg)
                    gemm_kg(acc, ldw(gU2_We, kg * 128 + j), hp, kg);
                const ulonglong2* xp = (const ulonglong2*)xtp[rp];
                #pragma unroll
                for (int kg = 0; kg < 16; ++kg)
                    gemm_kg(acc, ldw(gU2_Wi, kg * 128 + j), xp, kg);
            }
            scr[half * 512 + rp * 128 + j] = unp2(acc);
        }
        __syncthreads();

        if (tid < 512) {
            const int j = tid & 127, rp = tid >> 7;
            const float2 a = scr[rp * 128 + j], b = scr[512 + rp * 128 + j];
            t1p[rp][j] = make_float2(ftanh(a.x + b.x), ftanh(a.y + b.y));
        }
        __syncthreads();

        // s partials: k-split
        if (tid < 512) {
            const int f = tid & 63, rp = (tid >> 6) & 3, half = tid >> 8;
            u64 acc = half ? dup2(0.0f) : dup2(Vd_b[f]);
            const ulonglong2* tp = (const ulonglong2*)t1p[rp];
            const int k0 = half * 16;
            #pragma unroll 8
            for (int kg = k0; kg < k0 + 16; ++kg)
                gemm_kg(acc, ldw(gU2_Vd, kg * 64 + f), tp, kg);
            scr[1024 + half * 256 + rp * 64 + f] = unp2(acc);
        }
        __syncthreads();

        // softmax + x_in : warps 0..7
        if (wno < 8) {
            const int rp = wno >> 1, half = wno & 1;
            const float2 a0 = scr[1024 + rp * 64 + lane];
            const float2 b0 = scr[1280 + rp * 64 + lane];
            const float2 a1 = scr[1024 + rp * 64 + lane + 32];
            const float2 b1 = scr[1280 + rp * 64 + lane + 32];
            float v0 = half ? (a0.y + b0.y) : (a0.x + b0.x);
            float v1 = half ? (a1.y + b1.y) : (a1.x + b1.x);
            float mx = fmaxf(v0, v1);
            #pragma unroll
            for (int o = 16; o; o >>= 1) mx = fmaxf(mx, __shfl_xor_sync(~0u, mx, o));
            float e0 = __expf(v0 - mx), e1 = __expf(v1 - mx);
            float sm = e0 + e1;
            #pragma unroll
            for (int o = 16; o; o >>= 1) sm += __shfl_xor_sync(~0u, sm, o);
            const float inv = __fdividef(1.0f, sm);
            const float2 x0 = xtp[rp][lane], x1 = xtp[rp][lane + 32];
            ((float*)&xinp[rp][lane])[half]      = (half ? x0.y : x0.x) * e0 * inv;
            ((float*)&xinp[rp][lane + 32])[half] = (half ? x1.y : x1.x) * e1 * inv;
        }
        __syncthreads();

        // enc gates: thread = (c, rpg)
        {
            const int c = tid & 511, rpg = tid >> 9;
            const int ra = rpg * 2, rb = rpg * 2 + 1;
            const u64 bini = dup2(ebih[c] + ebhh[c]);
            u64 A0 = bini, A1 = bini;
            #pragma unroll 4
            for (int kg = 0; kg < 16; ++kg) {
                const float4 w = ldw(gU2_eWih, kg * 512 + c);
                gemm_kg(A0, w, (const ulonglong2*)xinp[ra], kg);
                gemm_kg(A1, w, (const ulonglong2*)xinp[rb], kg);
            }
            #pragma unroll 4
            for (int kg = 0; kg < 32; ++kg) {
                const float4 w = ldw(gU2_eWhh, kg * 512 + c);
                gemm_kg(A0, w, (const ulonglong2*)hcp[ra], kg);
                gemm_kg(A1, w, (const ulonglong2*)hcp[rb], kg);
            }
            scr[ra * 512 + c] = unp2(A0);
            scr[rb * 512 + c] = unp2(A1);
        }
        __syncthreads();

        // enc LSTM update
        {
            const int j = tid & 127, rp = (tid >> 7) & 3, half = tid >> 9;
            const float gi = ((const float*)&scr[rp * 512 + j      ])[half];
            const float gf = ((const float*)&scr[rp * 512 + j + 128])[half];
            const float gg = ((const float*)&scr[rp * 512 + j + 256])[half];
            const float go = ((const float*)&scr[rp * 512 + j + 384])[half];
            const float co = ((const float*)&hcp[rp][128 + j])[half];
            const float cn = fsigm(gf) * co + fsigm(gi) * ftanh(gg);
            const float hn = fsigm(go) * ftanh(cn);
            ((float*)&hcp[rp][j])[half]       = hn;
            ((float*)&hcp[rp][128 + j])[half] = cn;
        }
        __syncthreads();

        // mid gates
        {
            const int c = tid & 511, rpg = tid >> 9;
            const int ra = rpg * 2, rb = rpg * 2 + 1;
            const u64 bini = dup2(mbih[c] + mbhh[c]);
            u64 A0 = bini, A1 = bini;
            #pragma unroll 4
            for (int kg = 0; kg < 32; ++kg) {
                const float4 w = ldw(gU2_mWih, kg * 512 + c);
                gemm_kg(A0, w, (const ulonglong2*)hcp[ra], kg);
                gemm_kg(A1, w, (const ulonglong2*)hcp[rb], kg);
            }
            #pragma unroll 4
            for (int kg = 0; kg < 32; ++kg) {
                const float4 w = ldw(gU2_mWhh, kg * 512 + c);
                gemm_kg(A0, w, (const ulonglong2*)hmcp[ra], kg);
                gemm_kg(A1, w, (const ulonglong2*)hmcp[rb], kg);
            }
            scr[ra * 512 + c] = unp2(A0);
            scr[rb * 512 + c] = unp2(A1);
        }
        __syncthreads();

        // mid LSTM update + g_mid store
        {
            const int j = tid & 127, rp = (tid >> 7) & 3, half = tid >> 9;
            const float gi = ((const float*)&scr[rp * 512 + j      ])[half];
            const float gf = ((const float*)&scr[rp * 512 + j + 128])[half];
            const float gg = ((const float*)&scr[rp * 512 + j + 256])[half];
            const float go = ((const float*)&scr[rp * 512 + j + 384])[half];
            const float co = ((const float*)&hmcp[rp][128 + j])[half];
            const float cn = fsigm(gf) * co + fsigm(gi) * ftanh(gg);
            const float hn = fsigm(go) * ftanh(cn);
            ((float*)&hmcp[rp][j])[half]       = hn;
            ((float*)&hmcp[rp][128 + j])[half] = cn;
            ((float*)&g_midp[((p0 + rp) * TE + t) * NH + j])[half] = hn;
        }
        __syncthreads();
    }

    {
        const int j = tid & 127, rp = (tid >> 7) & 3, half = tid >> 9;
        ((float*)&g_hmp[(p0 + rp) * NH + j])[half] = ((const float*)&hmcp[rp][j])[half];
        ((float*)&g_cmp[(p0 + rp) * NH + j])[half] = ((const float*)&hmcp[rp][128 + j])[half];
    }
}

// ---------------- Kernel 2: wx_mid ----------------
__global__ __launch_bounds__(256, 1)
void k_wx(const float* __restrict__ Wx_b)
{
    __shared__ __align__(16) float2 msp[16][128];
    const int tid = threadIdx.x;
    const int ub  = blockIdx.x * 16;

    for (int i = tid; i < 16 * 128; i += 256)
        msp[i >> 7][i & 127] = g_midp[ub * NH + i];
    __syncthreads();

    const int j = tid & 127, rg = tid >> 7;
    const u64 bini = dup2(Wx_b[j]);
    u64 acc[8];
    #pragma unroll
    for (int u = 0; u < 8; ++u) acc[u] = bini;

    #pragma unroll 4
    for (int kg = 0; kg < 32; ++kg) {
        const float4 w = ldw(gU2_Wx, kg * 128 + j);
        #pragma unroll
        for (int u = 0; u < 8; ++u)
            gemm_kg(acc[u], w, (const ulonglong2*)msp[rg * 8 + u], kg);
    }
    #pragma unroll
    for (int u = 0; u < 8; ++u) {
        const int gu = ub + rg * 8 + u;
        const int pair = gu / TE, tt = gu % TE;
        const float2 r = unp2(acc[u]);
        g_wx[((2 * pair)     * TE + tt) * NH + j] = r.x;
        g_wx[((2 * pair + 1) * TE + tt) * NH + j] = r.y;
    }
}

// ---------------- Kernel 3: decoder (1024 threads) ----------------
__global__ __launch_bounds__(1024, 1)
void k_dec(const float* __restrict__ V_w,  const float* __restrict__ V_b,
           const float* __restrict__ dbih, const float* __restrict__ dbhh,
           const float* __restrict__ regw, const float* __restrict__ regb,
           float* __restrict__ out)
{
    __shared__ __align__(16) float2 hicp[4][256];
    __shared__ __align__(16) float2 qsp [4][128];
    __shared__ __align__(16) float2 ssp2[4][TE];
    __shared__ __align__(16) float2 dinp[4][128];
    __shared__ __align__(16) float2 scr [2048];

    const int tid = threadIdx.x;
    const int r0  = blockIdx.x * 8;
    const int p0  = blockIdx.x * 4;
    const int wno = tid >> 5, lane = tid & 31;

    const float4 vw4 = ((const float4*)V_w)[lane];
    const float  vb  = V_b[0];

    {
        const int rp = tid >> 8, k = tid & 255;
        hicp[rp][k] = (k < 128) ? g_hmp[(p0 + rp) * NH + k]
                                : g_cmp[(p0 + rp) * NH + (k - 128)];
    }
    __syncthreads();

    for (int td = 0; td < TD; ++td) {
        // q partials: k-split
        {
            const int j = tid & 127, rp = (tid >> 7) & 3, half = tid >> 9;
            u64 acc = dup2(0.0f);
            const ulonglong2* hp = (const ulonglong2*)hicp[rp];
            const int k0 = half * 32;
            #pragma unroll 8
            for (int kg = k0; kg < k0 + 32; ++kg)
                gemm_kg(acc, ldw(gU2_Wh, kg * 128 + j), hp, kg);
            scr[half * 512 + rp * 128 + j] = unp2(acc);
        }
        __syncthreads();
        if (tid < 512) {
            const int j = tid & 127, rp = tid >> 7;
            const float2 a = scr[rp * 128 + j], b = scr[512 + rp * 128 + j];
            qsp[rp][j] = make_float2(a.x + b.x, a.y + b.y);
        }
        __syncthreads();

        // scores
        for (int s = wno; s < 8 * TE; s += 32) {
            const int r = s / TE, tt = s % TE;
            const int rp = r >> 1, half = r & 1;
            const float4 x = ((const float4*)(g_wx + ((r0 + r) * TE + tt) * NH))[lane];
            const float2 q0 = qsp[rp][4 * lane],     q1 = qsp[rp][4 * lane + 1];
            const float2 q2 = qsp[rp][4 * lane + 2], q3 = qsp[rp][4 * lane + 3];
            float acc;
            acc =      ftanh((half ? q0.y : q0.x) + x.x) * vw4.x;
            acc = fmaf(ftanh((half ? q1.y : q1.x) + x.y), vw4.y, acc);
            acc = fmaf(ftanh((half ? q2.y : q2.x) + x.z), vw4.z, acc);
            acc = fmaf(ftanh((half ? q3.y : q3.x) + x.w), vw4.w, acc);
            #pragma unroll
            for (int o = 16; o; o >>= 1) acc += __shfl_xor_sync(~0u, acc, o);
            if (lane == 0) ((float*)&ssp2[rp][tt])[half] = acc + vb;
        }
        __syncthreads();

        // din partials: t-split
        {
            const int j = tid & 127, rp = (tid >> 7) & 3, half = tid >> 9;
            u64 acc = dup2(0.0f);
            const u64* sp = (const u64*)ssp2[rp];
            const float2* mp = g_midp + ((p0 + rp) * TE) * NH + j;
            const int t0 = half * 84;
            #pragma unroll 4
            for (int tt = t0; tt < t0 + 84; ++tt) {
                const u64 m2 = *(const u64*)(mp + tt * NH);
                ffma2(acc, sp[tt], m2);
            }
            scr[half * 512 + rp * 128 + j] = unp2(acc);
        }
        __syncthreads();
        if (tid < 512) {
            const int j = tid & 127, rp = tid >> 7;
            const float2 a = scr[rp * 128 + j], b = scr[512 + rp * 128 + j];
            dinp[rp][j] = make_float2(a.x + b.x, a.y + b.y);
        }
        __syncthreads();

        // dec gates
        {
            const int c = tid & 511, rpg = tid >> 9;
            const int ra = rpg * 2, rb = rpg * 2 + 1;
            const u64 bini = dup2(dbih[c] + dbhh[c]);
            u64 A0 = bini, A1 = bini;
            #pragma unroll 4
            for (int kg = 0; kg < 32; ++kg) {
                const float4 w = ldw(gU2_dWih, kg * 512 + c);
                gemm_kg(A0, w, (const ulonglong2*)dinp[ra], kg);
                gemm_kg(A1, w, (const ulonglong2*)dinp[rb], kg);
            }
            #pragma unroll 4
            for (int kg = 0; kg < 32; ++kg) {
                const float4 w = ldw(gU2_dWhh, kg * 512 + c);
                gemm_kg(A0, w, (const ulonglong2*)hicp[ra], kg);
                gemm_kg(A1, w, (const ulonglong2*)hicp[rb], kg);
            }
            scr[ra * 512 + c] = unp2(A0);
            scr[rb * 512 + c] = unp2(A1);
        }
        __syncthreads();

        // dec LSTM update
        {
            const int j = tid & 127, rp = (tid >> 7) & 3, half = tid >> 9;
            const float gi = ((const float*)&scr[rp * 512 + j      ])[half];
            const float gf = ((const float*)&scr[rp * 512 + j + 128])[half];
            const float gg = ((const float*)&scr[rp * 512 + j + 256])[half];
            const float go = ((const float*)&scr[rp * 512 + j + 384])[half];
            const float co = ((const float*)&hicp[rp][128 + j])[half];
            const float cn = fsigm(gf) * co + fsigm(gi) * ftanh(gg);
            const float hn = fsigm(go) * ftanh(cn);
            ((float*)&hicp[rp][j])[half]       = hn;
            ((float*)&hicp[rp][128 + j])[half] = cn;
        }
        __syncthreads();

        // out head
        if (wno < 8) {
            const int rp = wno >> 1, half = wno & 1;
            const float2 h0 = hicp[rp][lane],      h1 = hicp[rp][lane + 32];
            const float2 h2 = hicp[rp][lane + 64], h3 = hicp[rp][lane + 96];
            float acc =       (half ? h0.y : h0.x) * regw[lane];
            acc = fmaf((half ? h1.y : h1.x), regw[lane + 32], acc);
            acc = fmaf((half ? h2.y : h2.x), regw[lane + 64], acc);
            acc = fmaf((half ? h3.y : h3.x), regw[lane + 96], acc);
            #pragma unroll
            for (int o = 16; o; o >>= 1) acc += __shfl_xor_sync(~0u, acc, o);
            if (lane == 0) out[(r0 + wno) * TD + td] = acc + regb[0];
        }
        __syncthreads();
    }
}

extern "C" void kernel_launch(void* const* d_in, const int* in_sizes, int n_in,
                              void* d_out, int out_size)
{
    const float* X    = (const float*)d_in[0];
    const float* Wi_w = (const float*)d_in[2];
    const float* Wi_b = (const float*)d_in[3];
    const float* We_w = (const float*)d_in[4];
    const float* Vd_w = (const float*)d_in[5];
    const float* Vd_b = (const float*)d_in[6];
    const float* eWih = (const float*)d_in[7];
    const float* eWhh = (const float*)d_in[8];
    const float* ebih = (const float*)d_in[9];
    const float* ebhh = (const float*)d_in[10];
    const float* mWih = (const float*)d_in[11];
    const float* mWhh = (const float*)d_in[12];
    const float* mbih = (const float*)d_in[13];
    const float* mbhh = (const float*)d_in[14];
    const float* Wx_w = (const float*)d_in[15];
    const float* Wx_b = (const float*)d_in[16];
    const float* Wh_w = (const float*)d_in[17];
    const float* V_w  = (const float*)d_in[18];
    const float* V_b  = (const float*)d_in[19];
    const float* dWih = (const float*)d_in[20];
    const float* dWhh = (const float*)d_in[21];
    const float* dbih = (const float*)d_in[22];
    const float* dbhh = (const float*)d_in[23];
    const float* regw = (const float*)d_in[24];
    const float* regb = (const float*)d_in[25];

    k_tr<<<256, 256>>>(eWih, eWhh, mWih, mWhh, dWih, dWhh,
                       We_w, Wi_w, Vd_w, Wh_w, Wx_w);
    k_enc_mid<<<NB / 8, 1024>>>(X, Wi_b, Vd_b, ebih, ebhh, mbih, mbhh);
    k_wx<<<(NB / 2 * TE) / 16, 256>>>(Wx_b);
    k_dec<<<NB / 8, 1024>>>(V_w, V_b, dbih, dbhh, regw, regb, (float*)d_out);
}